// round 4
// baseline (speedup 1.0000x reference)
#include <cuda_runtime.h>
#include <cuda_fp16.h>
#include <cstdint>

#define BDIM 8
#define SDIM 4096
#define EDIM 256
#define HDIM 4
#define DK   64
#define MTOT (BDIM * SDIM)   // 32768

// ---------------- scratch (device globals; no runtime alloc) -------------------
__device__ __half g_xh[(size_t)MTOT * EDIM];
__device__ __half g_xl[(size_t)MTOT * EDIM];
__device__ __half g_yh[(size_t)MTOT * EDIM];
__device__ __half g_yl[(size_t)MTOT * EDIM];
__device__ float  g_q[(size_t)MTOT * EDIM];
__device__ float  g_k[(size_t)MTOT * EDIM];
__device__ float  g_v[(size_t)MTOT * EDIM];
__device__ __half g_wh[4][EDIM * EDIM];
__device__ __half g_wl[4][EDIM * EDIM];

// ---------------- helpers ------------------------------------------------------
__device__ __forceinline__ uint32_t smem_u32(const void* p) {
    uint32_t a;
    asm("{ .reg .u64 t; cvta.to.shared.u64 t, %1; cvt.u32.u64 %0, t; }" : "=r"(a) : "l"(p));
    return a;
}

#define CP_ASYNC16(smem, gmem) \
    asm volatile("cp.async.cg.shared.global [%0], [%1], 16;" :: "r"(smem), "l"(gmem))
#define CP_ASYNC_COMMIT() asm volatile("cp.async.commit_group;")
#define CP_ASYNC_WAIT(n)  asm volatile("cp.async.wait_group %0;" :: "n"(n))

#define LDMATRIX_X4(r0, r1, r2, r3, addr) \
    asm volatile("ldmatrix.sync.aligned.m8n8.x4.shared.b16 {%0,%1,%2,%3}, [%4];" \
        : "=r"(r0), "=r"(r1), "=r"(r2), "=r"(r3) : "r"(addr))

#define MMA16816(c, a, b0, b1) \
    asm volatile("mma.sync.aligned.m16n8k16.row.col.f32.f16.f16.f32 " \
        "{%0,%1,%2,%3}, {%4,%5,%6,%7}, {%8,%9}, {%0,%1,%2,%3};" \
        : "+f"((c)[0]), "+f"((c)[1]), "+f"((c)[2]), "+f"((c)[3]) \
        : "r"((a)[0]), "r"((a)[1]), "r"((a)[2]), "r"((a)[3]), "r"(b0), "r"(b1))

// ---------------- split: fp32 -> fp16 hi + fp16 lo ------------------------------
__global__ void split_kernel(const float4* __restrict__ src,
                             uint2* __restrict__ hi, uint2* __restrict__ lo, int n4)
{
    int i = blockIdx.x * blockDim.x + threadIdx.x;
    if (i >= n4) return;
    float4 v = src[i];
    __half h0 = __float2half_rn(v.x), h1 = __float2half_rn(v.y);
    __half h2 = __float2half_rn(v.z), h3 = __float2half_rn(v.w);
    __half2 ph0{h0, h1}, ph1{h2, h3};
    __half2 pl0{__float2half_rn(v.x - __half2float(h0)),
                __float2half_rn(v.y - __half2float(h1))};
    __half2 pl1{__float2half_rn(v.z - __half2float(h2)),
                __float2half_rn(v.w - __half2float(h3))};
    uint2 H, L;
    H.x = *(uint32_t*)&ph0; H.y = *(uint32_t*)&ph1;
    L.x = *(uint32_t*)&pl0; L.y = *(uint32_t*)&pl1;
    hi[i] = H; lo[i] = L;
}

// ---------------- HMMA GEMM: C[M,256] = (Ah+Al)(Wh+Wl)^T + bias -----------------
// CTA tile 128x128. W slice (128 rows x 256 cols, hi+lo) resident in smem.
// A tiles (128 x 64, hi+lo) double-buffered via cp.async.
#define BM 128
#define BN 128
#define BK 64
#define NKC (EDIM / BK)             // 4
#define GT 256
#define LDA 72                      // A tile row stride (halves)
#define LDW 264                     // W slice row stride (halves)
#define A_TILE (BM * LDA)           // 9216 halves
#define W_TILE (BN * LDW)           // 33792 halves
// smem layout (halves): [Wh][Wl][A(stage0 hi)][A(stage0 lo)][A(stage1 hi)][A(stage1 lo)]
#define OFF_WH 0
#define OFF_WL W_TILE
#define OFF_A  (2 * W_TILE)
#define SMEM_HALFS (2 * W_TILE + 4 * A_TILE)
#define SMEM_BYTES (SMEM_HALFS * 2)   // 208896

__device__ __forceinline__ void load_A_chunk(uint32_t sA, const __half* __restrict__ src,
                                             int m0, int k0, int tid)
{
    // 128 rows x 64 halves = 1024 16B-chunks, 4 per thread
#pragma unroll
    for (int i = 0; i < 4; i++) {
        const int c = tid + i * GT;
        const int row = c >> 3;
        const int col = (c & 7) << 3;
        CP_ASYNC16(sA + (uint32_t)(row * LDA + col) * 2,
                   src + (size_t)(m0 + row) * EDIM + k0 + col);
    }
}

__global__ __launch_bounds__(GT, 1)
void hmma_gemm_kernel(const __half* __restrict__ Ah,
                      const __half* __restrict__ Al,
                      const __half* __restrict__ Wh,
                      const __half* __restrict__ Wl,
                      const float* __restrict__ bias,
                      float* __restrict__ C)
{
    extern __shared__ __half smem[];
    const uint32_t sb = smem_u32(smem);
    const uint32_t sWh = sb + OFF_WH * 2;
    const uint32_t sWl = sb + OFF_WL * 2;

    const int tid = threadIdx.x;
    const int wid = tid >> 5;
    const int lane = tid & 31;
    const int m0 = blockIdx.y * BM;
    const int n0 = blockIdx.x * BN;
    const int warp_m = (wid & 3) * 32;
    const int warp_n = (wid >> 2) * 64;

    // ---- preload W slice (hi+lo): 128 rows x 256 halves each ----
#pragma unroll
    for (int i = 0; i < 16; i++) {
        const int c = tid + i * GT;          // 0..4095
        const int row = c >> 5;
        const int col = (c & 31) << 3;
        const uint32_t soff = (uint32_t)(row * LDW + col) * 2;
        const size_t goff = (size_t)(n0 + row) * EDIM + col;
        CP_ASYNC16(sWh + soff, Wh + goff);
        CP_ASYNC16(sWl + soff, Wl + goff);
    }
    CP_ASYNC_COMMIT();                        // group: W

    // ---- prologue: A chunk 0 into stage 0 ----
    load_A_chunk(sb + OFF_A * 2,                Ah, m0, 0, tid);
    load_A_chunk(sb + (OFF_A + A_TILE) * 2,     Al, m0, 0, tid);
    CP_ASYNC_COMMIT();                        // group: A0

    float acc[2][8][4];
#pragma unroll
    for (int i = 0; i < 2; i++)
#pragma unroll
        for (int j = 0; j < 8; j++)
#pragma unroll
            for (int r = 0; r < 4; r++) acc[i][j][r] = 0.0f;

    for (int kc = 0; kc < NKC; kc++) {
        const int cur = kc & 1;
        if (kc + 1 < NKC) {
            const int nxt = cur ^ 1;
            load_A_chunk(sb + (OFF_A + nxt * 2 * A_TILE) * 2,          Ah, m0, (kc + 1) * BK, tid);
            load_A_chunk(sb + (OFF_A + nxt * 2 * A_TILE + A_TILE) * 2, Al, m0, (kc + 1) * BK, tid);
            CP_ASYNC_COMMIT();
            CP_ASYNC_WAIT(1);                 // current stage (and W) complete
        } else {
            CP_ASYNC_WAIT(0);
        }
        __syncthreads();

        const uint32_t sAh = sb + (OFF_A + cur * 2 * A_TILE) * 2;
        const uint32_t sAl = sAh + A_TILE * 2;
        const int k0 = kc * BK;

#pragma unroll
        for (int ks = 0; ks < BK / 16; ks++) {
            const int k = ks * 16;
            uint32_t ah[2][4], al[2][4];
#pragma unroll
            for (int mf = 0; mf < 2; mf++) {
                const uint32_t off =
                    (uint32_t)((warp_m + mf * 16 + (lane & 15)) * LDA + k + ((lane >> 4) << 3)) * 2;
                LDMATRIX_X4(ah[mf][0], ah[mf][1], ah[mf][2], ah[mf][3], sAh + off);
                LDMATRIX_X4(al[mf][0], al[mf][1], al[mf][2], al[mf][3], sAl + off);
            }
#pragma unroll
            for (int np = 0; np < 4; np++) {
                const uint32_t boff =
                    (uint32_t)((warp_n + np * 16 + (lane & 7) + ((lane >> 4) << 3)) * LDW
                               + k0 + k + (((lane >> 3) & 1) << 3)) * 2;
                uint32_t bh[4], bl[4];
                LDMATRIX_X4(bh[0], bh[1], bh[2], bh[3], sWh + boff);
                LDMATRIX_X4(bl[0], bl[1], bl[2], bl[3], sWl + boff);
#pragma unroll
                for (int mf = 0; mf < 2; mf++) {
                    MMA16816(acc[mf][np * 2],     ah[mf], bh[0], bh[1]);
                    MMA16816(acc[mf][np * 2],     ah[mf], bl[0], bl[1]);
                    MMA16816(acc[mf][np * 2],     al[mf], bh[0], bh[1]);
                    MMA16816(acc[mf][np * 2 + 1], ah[mf], bh[2], bh[3]);
                    MMA16816(acc[mf][np * 2 + 1], ah[mf], bl[2], bl[3]);
                    MMA16816(acc[mf][np * 2 + 1], al[mf], bh[2], bh[3]);
                }
            }
        }
        __syncthreads();
    }

    // epilogue: C = acc + bias
#pragma unroll
    for (int mf = 0; mf < 2; mf++) {
        const int r0 = m0 + warp_m + mf * 16 + (lane >> 2);
#pragma unroll
        for (int nf = 0; nf < 8; nf++) {
            const int col = n0 + warp_n + nf * 8 + (lane & 3) * 2;
            const float b0 = bias[col], b1 = bias[col + 1];
            float2 v0{acc[mf][nf][0] + b0, acc[mf][nf][1] + b1};
            float2 v1{acc[mf][nf][2] + b0, acc[mf][nf][3] + b1};
            *(float2*)(C + (size_t)r0 * EDIM + col) = v0;
            *(float2*)(C + (size_t)(r0 + 8) * EDIM + col) = v1;
        }
    }
}

// ---------------- attention over heads; fused y -> (yh, yl) fp16 split ----------
__global__ __launch_bounds__(256)
void attn_heads_kernel(const float* __restrict__ q,
                       const float* __restrict__ k,
                       const float* __restrict__ v,
                       __half* __restrict__ yh,
                       __half* __restrict__ yl)
{
    const int t = blockIdx.x * 8 + (threadIdx.x >> 5);
    const int lane = threadIdx.x & 31;
    if (t >= MTOT) return;

    const float* qt = q + (size_t)t * EDIM;
    const float* kt = k + (size_t)t * EDIM;
    const float* vt = v + (size_t)t * EDIM;

    float qv[HDIM][2], kv[HDIM][2], vv[HDIM][2];
#pragma unroll
    for (int h = 0; h < HDIM; h++)
#pragma unroll
        for (int j = 0; j < 2; j++) {
            const int idx = h * DK + j * 32 + lane;
            qv[h][j] = qt[idx];
            kv[h][j] = kt[idx];
            vv[h][j] = vt[idx];
        }

    float s[HDIM][HDIM];
#pragma unroll
    for (int h = 0; h < HDIM; h++)
#pragma unroll
        for (int g = 0; g < HDIM; g++) {
            float p = qv[h][0] * kv[g][0] + qv[h][1] * kv[g][1];
#pragma unroll
            for (int off = 16; off > 0; off >>= 1)
                p += __shfl_xor_sync(0xFFFFFFFFu, p, off);
            s[h][g] = p * 0.125f;
        }

    float p[HDIM][HDIM];
#pragma unroll
    for (int h = 0; h < HDIM; h++) {
        float m = s[h][0];
#pragma unroll
        for (int g = 1; g < HDIM; g++) m = fmaxf(m, s[h][g]);
        float sum = 0.0f;
#pragma unroll
        for (int g = 0; g < HDIM; g++) { p[h][g] = __expf(s[h][g] - m); sum += p[h][g]; }
        const float inv = 1.0f / sum;
#pragma unroll
        for (int g = 0; g < HDIM; g++) p[h][g] *= inv;
    }

#pragma unroll
    for (int h = 0; h < HDIM; h++)
#pragma unroll
        for (int j = 0; j < 2; j++) {
            float acc = 0.0f;
#pragma unroll
            for (int g = 0; g < HDIM; g++) acc = fmaf(p[h][g], vv[g][j], acc);
            const int idx = h * DK + j * 32 + lane;
            __half hh = __float2half_rn(acc);
            yh[(size_t)t * EDIM + idx] = hh;
            yl[(size_t)t * EDIM + idx] = __float2half_rn(acc - __half2float(hh));
        }
}

// ---------------- launch --------------------------------------------------------
extern "C" void kernel_launch(void* const* d_in, const int* in_sizes, int n_in,
                              void* d_out, int out_size)
{
    const float* x  = (const float*)d_in[0];
    const float* Wq = (const float*)d_in[1];
    const float* bq = (const float*)d_in[2];
    const float* Wk = (const float*)d_in[3];
    const float* bk = (const float*)d_in[4];
    const float* Wv = (const float*)d_in[5];
    const float* bv = (const float*)d_in[6];
    const float* Wo = (const float*)d_in[7];
    const float* bo = (const float*)d_in[8];
    float* out = (float*)d_out;

    __half *xh, *xl, *yh, *yl;
    float *q, *k, *v;
    __half (*wh)[EDIM * EDIM], (*wl)[EDIM * EDIM];
    cudaGetSymbolAddress((void**)&xh, g_xh);
    cudaGetSymbolAddress((void**)&xl, g_xl);
    cudaGetSymbolAddress((void**)&yh, g_yh);
    cudaGetSymbolAddress((void**)&yl, g_yl);
    cudaGetSymbolAddress((void**)&q, g_q);
    cudaGetSymbolAddress((void**)&k, g_k);
    cudaGetSymbolAddress((void**)&v, g_v);
    cudaGetSymbolAddress((void**)&wh, g_wh);
    cudaGetSymbolAddress((void**)&wl, g_wl);

    cudaFuncSetAttribute(hmma_gemm_kernel,
                         cudaFuncAttributeMaxDynamicSharedMemorySize, SMEM_BYTES);

    // split inputs into fp16 hi/lo
    {
        int n4 = MTOT * EDIM / 4;
        split_kernel<<<n4 / 256, 256>>>((const float4*)x, (uint2*)xh, (uint2*)xl, n4);
        int w4 = EDIM * EDIM / 4;
        split_kernel<<<w4 / 256, 256>>>((const float4*)Wq, (uint2*)wh[0], (uint2*)wl[0], w4);
        split_kernel<<<w4 / 256, 256>>>((const float4*)Wk, (uint2*)wh[1], (uint2*)wl[1], w4);
        split_kernel<<<w4 / 256, 256>>>((const float4*)Wv, (uint2*)wh[2], (uint2*)wl[2], w4);
        split_kernel<<<w4 / 256, 256>>>((const float4*)Wo, (uint2*)wh[3], (uint2*)wl[3], w4);
    }

    dim3 ggrid(EDIM / BN, MTOT / BM);   // (2, 256)

    hmma_gemm_kernel<<<ggrid, GT, SMEM_BYTES>>>(xh, xl, wh[0], wl[0], bq, q);
    hmma_gemm_kernel<<<ggrid, GT, SMEM_BYTES>>>(xh, xl, wh[1], wl[1], bk, k);
    hmma_gemm_kernel<<<ggrid, GT, SMEM_BYTES>>>(xh, xl, wh[2], wl[2], bv, v);

    attn_heads_kernel<<<MTOT / 8, 256>>>(q, k, v, yh, yl);

    hmma_gemm_kernel<<<ggrid, GT, SMEM_BYTES>>>(yh, yl, wh[3], wl[3], bo, out);
}

// round 5
// speedup vs baseline: 1.1889x; 1.1889x over previous
#include <cuda_runtime.h>
#include <cuda_fp16.h>
#include <cstdint>

#define BDIM 8
#define SDIM 4096
#define EDIM 256
#define HDIM 4
#define DK   64
#define MTOT (BDIM * SDIM)   // 32768

// ---------------- scratch (device globals; no runtime alloc) -------------------
__device__ __half g_xh[(size_t)MTOT * EDIM];
__device__ __half g_xl[(size_t)MTOT * EDIM];
__device__ __half g_yh[(size_t)MTOT * EDIM];
__device__ __half g_yl[(size_t)MTOT * EDIM];
__device__ float  g_q[(size_t)MTOT * EDIM];
__device__ float  g_k[(size_t)MTOT * EDIM];
__device__ float  g_v[(size_t)MTOT * EDIM];
__device__ __half g_wh[4][EDIM * EDIM];
__device__ __half g_wl[4][EDIM * EDIM];

// ---------------- helpers ------------------------------------------------------
__device__ __forceinline__ uint32_t smem_u32(const void* p) {
    uint32_t a;
    asm("{ .reg .u64 t; cvta.to.shared.u64 t, %1; cvt.u32.u64 %0, t; }" : "=r"(a) : "l"(p));
    return a;
}

#define CP_ASYNC16(smem, gmem) \
    asm volatile("cp.async.cg.shared.global [%0], [%1], 16;" :: "r"(smem), "l"(gmem))
#define CP_ASYNC_COMMIT() asm volatile("cp.async.commit_group;")
#define CP_ASYNC_WAIT(n)  asm volatile("cp.async.wait_group %0;" :: "n"(n))

#define LDMATRIX_X4(r0, r1, r2, r3, addr) \
    asm volatile("ldmatrix.sync.aligned.m8n8.x4.shared.b16 {%0,%1,%2,%3}, [%4];" \
        : "=r"(r0), "=r"(r1), "=r"(r2), "=r"(r3) : "r"(addr))

#define MMA16816(c, a, b0, b1) \
    asm volatile("mma.sync.aligned.m16n8k16.row.col.f32.f16.f16.f32 " \
        "{%0,%1,%2,%3}, {%4,%5,%6,%7}, {%8,%9}, {%0,%1,%2,%3};" \
        : "+f"((c)[0]), "+f"((c)[1]), "+f"((c)[2]), "+f"((c)[3]) \
        : "r"((a)[0]), "r"((a)[1]), "r"((a)[2]), "r"((a)[3]), "r"(b0), "r"(b1))

// ---------------- split: fp32 -> fp16 hi + fp16 lo ------------------------------
__device__ __forceinline__ void split4(float4 v, uint2& H, uint2& L) {
    __half h0 = __float2half_rn(v.x), h1 = __float2half_rn(v.y);
    __half h2 = __float2half_rn(v.z), h3 = __float2half_rn(v.w);
    __half2 ph0{h0, h1}, ph1{h2, h3};
    __half2 pl0{__float2half_rn(v.x - __half2float(h0)),
                __float2half_rn(v.y - __half2float(h1))};
    __half2 pl1{__float2half_rn(v.z - __half2float(h2)),
                __float2half_rn(v.w - __half2float(h3))};
    H.x = *(uint32_t*)&ph0; H.y = *(uint32_t*)&ph1;
    L.x = *(uint32_t*)&pl0; L.y = *(uint32_t*)&pl1;
}

__global__ void split_kernel(const float4* __restrict__ src,
                             uint2* __restrict__ hi, uint2* __restrict__ lo, int n4)
{
    int i = blockIdx.x * blockDim.x + threadIdx.x;
    if (i >= n4) return;
    uint2 H, L;
    split4(src[i], H, L);
    hi[i] = H; lo[i] = L;
}

// all 4 weights in one launch; dst hi/lo are the contiguous g_wh/g_wl arrays
__global__ void split_w_kernel(const float4* __restrict__ s0, const float4* __restrict__ s1,
                               const float4* __restrict__ s2, const float4* __restrict__ s3,
                               uint2* __restrict__ hi, uint2* __restrict__ lo)
{
    int i = blockIdx.x * blockDim.x + threadIdx.x;     // 0 .. 4*16384-1
    int which = i >> 14;
    int j = i & 16383;
    const float4* src = which == 0 ? s0 : which == 1 ? s1 : which == 2 ? s2 : s3;
    uint2 H, L;
    split4(src[j], H, L);
    hi[i] = H; lo[i] = L;
}

// ---------------- HMMA GEMM ------------------------------------------------------
// CTA tile 128x128, BK=32, 2-stage cp.async double buffer, 8 warps (4m x 2n).
// grid.x selects {weight, n-tile}; supports fused QKV (3 weights) or single.
#define BM 128
#define BN 128
#define BK 32
#define NKC (EDIM / BK)             // 8
#define GT 256
#define LDA 40                      // padded row stride (halves)
#define TILE (BM * LDA)             // 5120 halves
#define STAGE (4 * TILE)            // Ah,Al,Wh,Wl
#define SMEM_BYTES (2 * STAGE * 2)  // 81920

__device__ __forceinline__ void load_stage(uint32_t st,
                                           const __half* __restrict__ Ah,
                                           const __half* __restrict__ Al,
                                           const __half* __restrict__ Wh,
                                           const __half* __restrict__ Wl,
                                           int m0, int n0, int k0, int tid)
{
#pragma unroll
    for (int i = 0; i < 2; i++) {
        const int c = tid + i * GT;          // 0..511
        const int row = c >> 2;
        const int col = (c & 3) << 3;
        const uint32_t soff = (uint32_t)(row * LDA + col) * 2;
        const size_t aoff = (size_t)(m0 + row) * EDIM + k0 + col;
        const size_t woff = (size_t)(n0 + row) * EDIM + k0 + col;
        CP_ASYNC16(st + soff, Ah + aoff);
        CP_ASYNC16(st + TILE * 2 + soff, Al + aoff);
        CP_ASYNC16(st + 2 * TILE * 2 + soff, Wh + woff);
        CP_ASYNC16(st + 3 * TILE * 2 + soff, Wl + woff);
    }
}

__global__ __launch_bounds__(GT, 2)
void hmma_gemm_kernel(const __half* __restrict__ Ah,
                      const __half* __restrict__ Al,
                      const __half* __restrict__ Wh_all,
                      const __half* __restrict__ Wl_all,
                      const float* __restrict__ b0p,
                      const float* __restrict__ b1p,
                      const float* __restrict__ b2p,
                      float* __restrict__ o0,
                      float* __restrict__ o1,
                      float* __restrict__ o2,
                      int wbase)
{
    extern __shared__ __half smem[];
    const uint32_t sb = smem_u32(smem);

    const int tid = threadIdx.x;
    const int wid = tid >> 5;
    const int lane = tid & 31;
    const int sel = blockIdx.x >> 1;
    const int n0 = (blockIdx.x & 1) * BN;
    const int m0 = blockIdx.y * BM;
    const int warp_m = (wid & 3) * 32;
    const int warp_n = (wid >> 2) * 64;

    const __half* Wh = Wh_all + (size_t)(wbase + sel) * EDIM * EDIM;
    const __half* Wl = Wl_all + (size_t)(wbase + sel) * EDIM * EDIM;
    const float* bias = sel == 0 ? b0p : (sel == 1 ? b1p : b2p);
    float* C = sel == 0 ? o0 : (sel == 1 ? o1 : o2);

    // prologue: chunks 0 and 1 into stages 0 and 1
    load_stage(sb, Ah, Al, Wh, Wl, m0, n0, 0, tid);
    CP_ASYNC_COMMIT();
    load_stage(sb + STAGE * 2, Ah, Al, Wh, Wl, m0, n0, BK, tid);
    CP_ASYNC_COMMIT();

    float acc[2][8][4];
#pragma unroll
    for (int i = 0; i < 2; i++)
#pragma unroll
        for (int j = 0; j < 8; j++)
#pragma unroll
            for (int r = 0; r < 4; r++) acc[i][j][r] = 0.0f;

    for (int kc = 0; kc < NKC; kc++) {
        if (kc < NKC - 1) CP_ASYNC_WAIT(1); else CP_ASYNC_WAIT(0);
        __syncthreads();

        const uint32_t st = sb + (kc & 1) * STAGE * 2;
        const uint32_t sAh = st;
        const uint32_t sAl = st + TILE * 2;
        const uint32_t sWh = st + 2 * TILE * 2;
        const uint32_t sWl = st + 3 * TILE * 2;

#pragma unroll
        for (int ks = 0; ks < BK / 16; ks++) {
            const int k = ks * 16;
            uint32_t ah[2][4], al[2][4];
#pragma unroll
            for (int mf = 0; mf < 2; mf++) {
                const uint32_t off =
                    (uint32_t)((warp_m + mf * 16 + (lane & 15)) * LDA + k + ((lane >> 4) << 3)) * 2;
                LDMATRIX_X4(ah[mf][0], ah[mf][1], ah[mf][2], ah[mf][3], sAh + off);
                LDMATRIX_X4(al[mf][0], al[mf][1], al[mf][2], al[mf][3], sAl + off);
            }
#pragma unroll
            for (int np = 0; np < 4; np++) {
                const uint32_t boff =
                    (uint32_t)((warp_n + np * 16 + (lane & 7) + ((lane >> 4) << 3)) * LDA
                               + k + (((lane >> 3) & 1) << 3)) * 2;
                uint32_t bh[4], bl[4];
                LDMATRIX_X4(bh[0], bh[1], bh[2], bh[3], sWh + boff);
                LDMATRIX_X4(bl[0], bl[1], bl[2], bl[3], sWl + boff);
#pragma unroll
                for (int mf = 0; mf < 2; mf++) {
                    MMA16816(acc[mf][np * 2],     ah[mf], bh[0], bh[1]);
                    MMA16816(acc[mf][np * 2],     ah[mf], bl[0], bl[1]);
                    MMA16816(acc[mf][np * 2],     al[mf], bh[0], bh[1]);
                    MMA16816(acc[mf][np * 2 + 1], ah[mf], bh[2], bh[3]);
                    MMA16816(acc[mf][np * 2 + 1], ah[mf], bl[2], bl[3]);
                    MMA16816(acc[mf][np * 2 + 1], al[mf], bh[2], bh[3]);
                }
            }
        }
        __syncthreads();
        if (kc + 2 < NKC) {
            load_stage(st, Ah, Al, Wh, Wl, m0, n0, (kc + 2) * BK, tid);
            CP_ASYNC_COMMIT();
        }
    }

    // epilogue: C = acc + bias
#pragma unroll
    for (int mf = 0; mf < 2; mf++) {
        const int r0 = m0 + warp_m + mf * 16 + (lane >> 2);
#pragma unroll
        for (int nf = 0; nf < 8; nf++) {
            const int col = n0 + warp_n + nf * 8 + (lane & 3) * 2;
            const float b0 = bias[col], b1 = bias[col + 1];
            float2 v0{acc[mf][nf][0] + b0, acc[mf][nf][1] + b1};
            float2 v1{acc[mf][nf][2] + b0, acc[mf][nf][3] + b1};
            *(float2*)(C + (size_t)r0 * EDIM + col) = v0;
            *(float2*)(C + (size_t)(r0 + 8) * EDIM + col) = v1;
        }
    }
}

// ---------------- attention over heads; fused y -> (yh, yl) fp16 split ----------
__global__ __launch_bounds__(256)
void attn_heads_kernel(const float* __restrict__ q,
                       const float* __restrict__ k,
                       const float* __restrict__ v,
                       __half* __restrict__ yh,
                       __half* __restrict__ yl)
{
    const int t = blockIdx.x * 8 + (threadIdx.x >> 5);
    const int lane = threadIdx.x & 31;
    if (t >= MTOT) return;

    const float* qt = q + (size_t)t * EDIM;
    const float* kt = k + (size_t)t * EDIM;
    const float* vt = v + (size_t)t * EDIM;

    float qv[HDIM][2], kv[HDIM][2], vv[HDIM][2];
#pragma unroll
    for (int h = 0; h < HDIM; h++)
#pragma unroll
        for (int j = 0; j < 2; j++) {
            const int idx = h * DK + j * 32 + lane;
            qv[h][j] = qt[idx];
            kv[h][j] = kt[idx];
            vv[h][j] = vt[idx];
        }

    float s[HDIM][HDIM];
#pragma unroll
    for (int h = 0; h < HDIM; h++)
#pragma unroll
        for (int g = 0; g < HDIM; g++) {
            float p = qv[h][0] * kv[g][0] + qv[h][1] * kv[g][1];
#pragma unroll
            for (int off = 16; off > 0; off >>= 1)
                p += __shfl_xor_sync(0xFFFFFFFFu, p, off);
            s[h][g] = p * 0.125f;
        }

    float p[HDIM][HDIM];
#pragma unroll
    for (int h = 0; h < HDIM; h++) {
        float m = s[h][0];
#pragma unroll
        for (int g = 1; g < HDIM; g++) m = fmaxf(m, s[h][g]);
        float sum = 0.0f;
#pragma unroll
        for (int g = 0; g < HDIM; g++) { p[h][g] = __expf(s[h][g] - m); sum += p[h][g]; }
        const float inv = 1.0f / sum;
#pragma unroll
        for (int g = 0; g < HDIM; g++) p[h][g] *= inv;
    }

#pragma unroll
    for (int h = 0; h < HDIM; h++)
#pragma unroll
        for (int j = 0; j < 2; j++) {
            float acc = 0.0f;
#pragma unroll
            for (int g = 0; g < HDIM; g++) acc = fmaf(p[h][g], vv[g][j], acc);
            const int idx = h * DK + j * 32 + lane;
            __half hh = __float2half_rn(acc);
            yh[(size_t)t * EDIM + idx] = hh;
            yl[(size_t)t * EDIM + idx] = __float2half_rn(acc - __half2float(hh));
        }
}

// ---------------- launch --------------------------------------------------------
extern "C" void kernel_launch(void* const* d_in, const int* in_sizes, int n_in,
                              void* d_out, int out_size)
{
    const float* x  = (const float*)d_in[0];
    const float* Wq = (const float*)d_in[1];
    const float* bq = (const float*)d_in[2];
    const float* Wk = (const float*)d_in[3];
    const float* bk = (const float*)d_in[4];
    const float* Wv = (const float*)d_in[5];
    const float* bv = (const float*)d_in[6];
    const float* Wo = (const float*)d_in[7];
    const float* bo = (const float*)d_in[8];
    float* out = (float*)d_out;

    __half *xh, *xl, *yh, *yl;
    float *q, *k, *v;
    __half (*wh)[EDIM * EDIM], (*wl)[EDIM * EDIM];
    cudaGetSymbolAddress((void**)&xh, g_xh);
    cudaGetSymbolAddress((void**)&xl, g_xl);
    cudaGetSymbolAddress((void**)&yh, g_yh);
    cudaGetSymbolAddress((void**)&yl, g_yl);
    cudaGetSymbolAddress((void**)&q, g_q);
    cudaGetSymbolAddress((void**)&k, g_k);
    cudaGetSymbolAddress((void**)&v, g_v);
    cudaGetSymbolAddress((void**)&wh, g_wh);
    cudaGetSymbolAddress((void**)&wl, g_wl);

    cudaFuncSetAttribute(hmma_gemm_kernel,
                         cudaFuncAttributeMaxDynamicSharedMemorySize, SMEM_BYTES);

    // splits
    {
        int n4 = MTOT * EDIM / 4;
        split_kernel<<<n4 / 256, 256>>>((const float4*)x, (uint2*)xh, (uint2*)xl, n4);
        split_w_kernel<<<256, 256>>>((const float4*)Wq, (const float4*)Wk,
                                     (const float4*)Wv, (const float4*)Wo,
                                     (uint2*)wh[0], (uint2*)wl[0]);
    }

    // fused Q,K,V GEMM: grid.x = 3 weights x 2 n-tiles
    {
        dim3 grid(6, MTOT / BM);
        hmma_gemm_kernel<<<grid, GT, SMEM_BYTES>>>(
            xh, xl, wh[0], wl[0], bq, bk, bv, q, k, v, 0);
    }

    attn_heads_kernel<<<MTOT / 8, 256>>>(q, k, v, yh, yl);

    // output GEMM
    {
        dim3 grid(2, MTOT / BM);
        hmma_gemm_kernel<<<grid, GT, SMEM_BYTES>>>(
            yh, yl, wh[0], wl[0], bo, bo, bo, out, out, out, 3);
    }
}

// round 6
// speedup vs baseline: 1.2454x; 1.0475x over previous
#include <cuda_runtime.h>
#include <cuda_fp16.h>
#include <cstdint>

#define BDIM 8
#define SDIM 4096
#define EDIM 256
#define HDIM 4
#define DK   64
#define MTOT (BDIM * SDIM)   // 32768

// ---------------- scratch (device globals; no runtime alloc) -------------------
__device__ __half g_xh[(size_t)MTOT * EDIM];
__device__ __half g_xl[(size_t)MTOT * EDIM];
__device__ __half g_yh[(size_t)MTOT * EDIM];
__device__ __half g_yl[(size_t)MTOT * EDIM];
__device__ float  g_q[(size_t)MTOT * EDIM];
__device__ float  g_k[(size_t)MTOT * EDIM];
__device__ float  g_v[(size_t)MTOT * EDIM];
__device__ __half g_wh[4][EDIM * EDIM];
__device__ __half g_wl[4][EDIM * EDIM];

// ---------------- helpers ------------------------------------------------------
__device__ __forceinline__ uint32_t smem_u32(const void* p) {
    uint32_t a;
    asm("{ .reg .u64 t; cvta.to.shared.u64 t, %1; cvt.u32.u64 %0, t; }" : "=r"(a) : "l"(p));
    return a;
}

#define CP_ASYNC16(smem, gmem) \
    asm volatile("cp.async.cg.shared.global [%0], [%1], 16;" :: "r"(smem), "l"(gmem))
#define CP_ASYNC_COMMIT() asm volatile("cp.async.commit_group;")
#define CP_ASYNC_WAIT(n)  asm volatile("cp.async.wait_group %0;" :: "n"(n))

#define LDMATRIX_X4(r0, r1, r2, r3, addr) \
    asm volatile("ldmatrix.sync.aligned.m8n8.x4.shared.b16 {%0,%1,%2,%3}, [%4];" \
        : "=r"(r0), "=r"(r1), "=r"(r2), "=r"(r3) : "r"(addr))

#define MMA16816(c, a, b0, b1) \
    asm volatile("mma.sync.aligned.m16n8k16.row.col.f32.f16.f16.f32 " \
        "{%0,%1,%2,%3}, {%4,%5,%6,%7}, {%8,%9}, {%0,%1,%2,%3};" \
        : "+f"((c)[0]), "+f"((c)[1]), "+f"((c)[2]), "+f"((c)[3]) \
        : "r"((a)[0]), "r"((a)[1]), "r"((a)[2]), "r"((a)[3]), "r"(b0), "r"(b1))

// ---------------- split: fp32 -> fp16 hi + fp16 lo ------------------------------
__device__ __forceinline__ void split4(float4 v, uint2& H, uint2& L) {
    __half h0 = __float2half_rn(v.x), h1 = __float2half_rn(v.y);
    __half h2 = __float2half_rn(v.z), h3 = __float2half_rn(v.w);
    __half2 ph0{h0, h1}, ph1{h2, h3};
    __half2 pl0{__float2half_rn(v.x - __half2float(h0)),
                __float2half_rn(v.y - __half2float(h1))};
    __half2 pl1{__float2half_rn(v.z - __half2float(h2)),
                __float2half_rn(v.w - __half2float(h3))};
    H.x = *(uint32_t*)&ph0; H.y = *(uint32_t*)&ph1;
    L.x = *(uint32_t*)&pl0; L.y = *(uint32_t*)&pl1;
}

// one launch splits x AND all 4 weight matrices
#define X4   (MTOT * EDIM / 4)          // 2097152 float4
#define W4   (EDIM * EDIM / 4)          // 16384 float4 per weight
#define ALL4 (X4 + 4 * W4)              // 2162688

__global__ void split_all_kernel(const float4* __restrict__ x,
                                 const float4* __restrict__ w0, const float4* __restrict__ w1,
                                 const float4* __restrict__ w2, const float4* __restrict__ w3,
                                 uint2* __restrict__ xhi, uint2* __restrict__ xlo,
                                 uint2* __restrict__ whi, uint2* __restrict__ wlo)
{
    int i = blockIdx.x * blockDim.x + threadIdx.x;
    if (i >= ALL4) return;
    uint2 H, L;
    if (i < X4) {
        split4(x[i], H, L);
        xhi[i] = H; xlo[i] = L;
    } else {
        int j = i - X4;
        int which = j >> 14;
        int idx = j & 16383;
        const float4* src = which == 0 ? w0 : which == 1 ? w1 : which == 2 ? w2 : w3;
        split4(src[idx], H, L);
        whi[j] = H; wlo[j] = L;
    }
}

// ---------------- HMMA GEMM ------------------------------------------------------
// CTA tile 128x128, BK=32, 2-stage cp.async double buffer, 8 warps (4m x 2n).
#define BM 128
#define BN 128
#define BK 32
#define NKC (EDIM / BK)             // 8
#define GT 256
#define LDA 40                      // padded row stride (halves)
#define TILE (BM * LDA)             // 5120 halves
#define STAGE (4 * TILE)            // Ah,Al,Wh,Wl
#define SMEM_BYTES (2 * STAGE * 2 + 1024)  // stages + bias

__device__ __forceinline__ void load_stage(uint32_t st,
                                           const __half* __restrict__ Ah,
                                           const __half* __restrict__ Al,
                                           const __half* __restrict__ Wh,
                                           const __half* __restrict__ Wl,
                                           int m0, int n0, int k0, int tid)
{
#pragma unroll
    for (int i = 0; i < 2; i++) {
        const int c = tid + i * GT;          // 0..511
        const int row = c >> 2;
        const int col = (c & 3) << 3;
        const uint32_t soff = (uint32_t)(row * LDA + col) * 2;
        const size_t aoff = (size_t)(m0 + row) * EDIM + k0 + col;
        const size_t woff = (size_t)(n0 + row) * EDIM + k0 + col;
        CP_ASYNC16(st + soff, Ah + aoff);
        CP_ASYNC16(st + TILE * 2 + soff, Al + aoff);
        CP_ASYNC16(st + 2 * TILE * 2 + soff, Wh + woff);
        CP_ASYNC16(st + 3 * TILE * 2 + soff, Wl + woff);
    }
}

__global__ __launch_bounds__(GT, 2)
void hmma_gemm_kernel(const __half* __restrict__ Ah,
                      const __half* __restrict__ Al,
                      const __half* __restrict__ Wh_all,
                      const __half* __restrict__ Wl_all,
                      const float* __restrict__ b0p,
                      const float* __restrict__ b1p,
                      const float* __restrict__ b2p,
                      float* __restrict__ o0,
                      float* __restrict__ o1,
                      float* __restrict__ o2,
                      int wbase)
{
    extern __shared__ __half smem[];
    const uint32_t sb = smem_u32(smem);
    float* sbias = (float*)(smem + 2 * STAGE);

    const int tid = threadIdx.x;
    const int wid = tid >> 5;
    const int lane = tid & 31;
    const int sel = blockIdx.x >> 1;
    const int n0 = (blockIdx.x & 1) * BN;
    const int m0 = blockIdx.y * BM;
    const int warp_m = (wid & 3) * 32;
    const int warp_n = (wid >> 2) * 64;

    const __half* Wh = Wh_all + (size_t)(wbase + sel) * EDIM * EDIM;
    const __half* Wl = Wl_all + (size_t)(wbase + sel) * EDIM * EDIM;
    const float* bias = sel == 0 ? b0p : (sel == 1 ? b1p : b2p);
    float* C = sel == 0 ? o0 : (sel == 1 ? o1 : o2);

    // prologue: chunks 0 and 1 into stages 0 and 1; bias to smem
    load_stage(sb, Ah, Al, Wh, Wl, m0, n0, 0, tid);
    CP_ASYNC_COMMIT();
    load_stage(sb + STAGE * 2, Ah, Al, Wh, Wl, m0, n0, BK, tid);
    CP_ASYNC_COMMIT();
    if (tid < 128) sbias[tid] = bias[n0 + tid];

    float acc[2][8][4];
#pragma unroll
    for (int i = 0; i < 2; i++)
#pragma unroll
        for (int j = 0; j < 8; j++)
#pragma unroll
            for (int r = 0; r < 4; r++) acc[i][j][r] = 0.0f;

    for (int kc = 0; kc < NKC; kc++) {
        if (kc < NKC - 1) CP_ASYNC_WAIT(1); else CP_ASYNC_WAIT(0);
        __syncthreads();

        const uint32_t st = sb + (kc & 1) * STAGE * 2;
        const uint32_t sAh = st;
        const uint32_t sAl = st + TILE * 2;
        const uint32_t sWh = st + 2 * TILE * 2;
        const uint32_t sWl = st + 3 * TILE * 2;

#pragma unroll
        for (int ks = 0; ks < BK / 16; ks++) {
            const int k = ks * 16;
            uint32_t ah[2][4], al[2][4];
#pragma unroll
            for (int mf = 0; mf < 2; mf++) {
                const uint32_t off =
                    (uint32_t)((warp_m + mf * 16 + (lane & 15)) * LDA + k + ((lane >> 4) << 3)) * 2;
                LDMATRIX_X4(ah[mf][0], ah[mf][1], ah[mf][2], ah[mf][3], sAh + off);
                LDMATRIX_X4(al[mf][0], al[mf][1], al[mf][2], al[mf][3], sAl + off);
            }
#pragma unroll
            for (int np = 0; np < 4; np++) {
                const uint32_t boff =
                    (uint32_t)((warp_n + np * 16 + (lane & 7) + ((lane >> 4) << 3)) * LDA
                               + k + (((lane >> 3) & 1) << 3)) * 2;
                uint32_t bh[4], bl[4];
                LDMATRIX_X4(bh[0], bh[1], bh[2], bh[3], sWh + boff);
                LDMATRIX_X4(bl[0], bl[1], bl[2], bl[3], sWl + boff);
#pragma unroll
                for (int mf = 0; mf < 2; mf++) {
                    MMA16816(acc[mf][np * 2],     ah[mf], bh[0], bh[1]);
                    MMA16816(acc[mf][np * 2],     ah[mf], bl[0], bl[1]);
                    MMA16816(acc[mf][np * 2],     al[mf], bh[0], bh[1]);
                    MMA16816(acc[mf][np * 2 + 1], ah[mf], bh[2], bh[3]);
                    MMA16816(acc[mf][np * 2 + 1], ah[mf], bl[2], bl[3]);
                    MMA16816(acc[mf][np * 2 + 1], al[mf], bh[2], bh[3]);
                }
            }
        }
        __syncthreads();
        if (kc + 2 < NKC) {
            load_stage(st, Ah, Al, Wh, Wl, m0, n0, (kc + 2) * BK, tid);
            CP_ASYNC_COMMIT();
        }
    }

    // epilogue: C = acc + bias (bias from smem)
#pragma unroll
    for (int mf = 0; mf < 2; mf++) {
        const int r0 = m0 + warp_m + mf * 16 + (lane >> 2);
#pragma unroll
        for (int nf = 0; nf < 8; nf++) {
            const int colL = warp_n + nf * 8 + (lane & 3) * 2;
            const float b0 = sbias[colL], b1 = sbias[colL + 1];
            const int col = n0 + colL;
            float2 v0{acc[mf][nf][0] + b0, acc[mf][nf][1] + b1};
            float2 v1{acc[mf][nf][2] + b0, acc[mf][nf][3] + b1};
            *(float2*)(C + (size_t)r0 * EDIM + col) = v0;
            *(float2*)(C + (size_t)(r0 + 8) * EDIM + col) = v1;
        }
    }
}

// ---------------- attention over heads; fused y -> (yh, yl) fp16 split ----------
// one warp per token, float2-vectorized: lane covers dims [2*lane, 2*lane+1] of each head
__global__ __launch_bounds__(256)
void attn_heads_kernel(const float* __restrict__ q,
                       const float* __restrict__ k,
                       const float* __restrict__ v,
                       __half* __restrict__ yh,
                       __half* __restrict__ yl)
{
    const int t = blockIdx.x * 8 + (threadIdx.x >> 5);
    const int lane = threadIdx.x & 31;

    const float2* qt = (const float2*)(q + (size_t)t * EDIM) + lane;
    const float2* kt = (const float2*)(k + (size_t)t * EDIM) + lane;
    const float2* vt = (const float2*)(v + (size_t)t * EDIM) + lane;

    float2 qv[HDIM], kv[HDIM], vv[HDIM];
#pragma unroll
    for (int h = 0; h < HDIM; h++) {
        qv[h] = qt[h * 32];
        kv[h] = kt[h * 32];
        vv[h] = vt[h * 32];
    }

    float s[HDIM][HDIM];
#pragma unroll
    for (int h = 0; h < HDIM; h++)
#pragma unroll
        for (int g = 0; g < HDIM; g++) {
            float p = qv[h].x * kv[g].x + qv[h].y * kv[g].y;
#pragma unroll
            for (int off = 16; off > 0; off >>= 1)
                p += __shfl_xor_sync(0xFFFFFFFFu, p, off);
            s[h][g] = p * 0.125f;
        }

    float p[HDIM][HDIM];
#pragma unroll
    for (int h = 0; h < HDIM; h++) {
        float m = s[h][0];
#pragma unroll
        for (int g = 1; g < HDIM; g++) m = fmaxf(m, s[h][g]);
        float sum = 0.0f;
#pragma unroll
        for (int g = 0; g < HDIM; g++) { p[h][g] = __expf(s[h][g] - m); sum += p[h][g]; }
        const float inv = 1.0f / sum;
#pragma unroll
        for (int g = 0; g < HDIM; g++) p[h][g] *= inv;
    }

    __half2* yhp = (__half2*)(yh + (size_t)t * EDIM) + lane;
    __half2* ylp = (__half2*)(yl + (size_t)t * EDIM) + lane;
#pragma unroll
    for (int h = 0; h < HDIM; h++) {
        float ax = 0.0f, ay = 0.0f;
#pragma unroll
        for (int g = 0; g < HDIM; g++) {
            ax = fmaf(p[h][g], vv[g].x, ax);
            ay = fmaf(p[h][g], vv[g].y, ay);
        }
        __half hx = __float2half_rn(ax), hy = __float2half_rn(ay);
        yhp[h * 32] = __half2{hx, hy};
        ylp[h * 32] = __half2{__float2half_rn(ax - __half2float(hx)),
                              __float2half_rn(ay - __half2float(hy))};
    }
}

// ---------------- launch --------------------------------------------------------
extern "C" void kernel_launch(void* const* d_in, const int* in_sizes, int n_in,
                              void* d_out, int out_size)
{
    const float* x  = (const float*)d_in[0];
    const float* Wq = (const float*)d_in[1];
    const float* bq = (const float*)d_in[2];
    const float* Wk = (const float*)d_in[3];
    const float* bk = (const float*)d_in[4];
    const float* Wv = (const float*)d_in[5];
    const float* bv = (const float*)d_in[6];
    const float* Wo = (const float*)d_in[7];
    const float* bo = (const float*)d_in[8];
    float* out = (float*)d_out;

    __half *xh, *xl, *yh, *yl;
    float *q, *k, *v;
    __half (*wh)[EDIM * EDIM], (*wl)[EDIM * EDIM];
    cudaGetSymbolAddress((void**)&xh, g_xh);
    cudaGetSymbolAddress((void**)&xl, g_xl);
    cudaGetSymbolAddress((void**)&yh, g_yh);
    cudaGetSymbolAddress((void**)&yl, g_yl);
    cudaGetSymbolAddress((void**)&q, g_q);
    cudaGetSymbolAddress((void**)&k, g_k);
    cudaGetSymbolAddress((void**)&v, g_v);
    cudaGetSymbolAddress((void**)&wh, g_wh);
    cudaGetSymbolAddress((void**)&wl, g_wl);

    cudaFuncSetAttribute(hmma_gemm_kernel,
                         cudaFuncAttributeMaxDynamicSharedMemorySize, SMEM_BYTES);

    // one split launch for x + all weights
    split_all_kernel<<<(ALL4 + 255) / 256, 256>>>(
        (const float4*)x, (const float4*)Wq, (const float4*)Wk,
        (const float4*)Wv, (const float4*)Wo,
        (uint2*)xh, (uint2*)xl, (uint2*)wh[0], (uint2*)wl[0]);

    // fused Q,K,V GEMM: grid.x = 3 weights x 2 n-tiles
    {
        dim3 grid(6, MTOT / BM);
        hmma_gemm_kernel<<<grid, GT, SMEM_BYTES>>>(
            xh, xl, wh[0], wl[0], bq, bk, bv, q, k, v, 0);
    }

    attn_heads_kernel<<<MTOT / 8, 256>>>(q, k, v, yh, yl);

    // output GEMM
    {
        dim3 grid(2, MTOT / BM);
        hmma_gemm_kernel<<<grid, GT, SMEM_BYTES>>>(
            yh, yl, wh[0], wl[0], bo, bo, bo, out, out, out, 3);
    }
}